// round 14
// baseline (speedup 1.0000x reference)
#include <cuda_runtime.h>
#include <cuda_bf16.h>
#include <cuda_fp16.h>
#include <cstdint>

#define N_NODES 50000
#define E_EDGES 800000
#define EN_TOT  (E_EDGES + N_NODES)
#define IN_CH   256
#define OUT_CH  64
#define HEADS   4
#define HC      256
#define NEG_SLOPE 0.2f
#define MBLK    391            // ceil(50000/128)
#define SBLK    196            // ceil(50000/256)
#define ECHUNK  8              // edges per group in k_sum
#define SCHUNK  32             // edges per group in k_scatter

// ---------------- device scratch ---------------------------------------------
__device__ uint4    g_Af[MBLK * 8192];      // A frags [mb][kc8][hl2][ks2][mt8][lane32]
__device__ uint4    g_Bf[5 * 4096];         // B frags [nb5][kc8][ks2][nt8][lane32]
__device__ __half2  g_outh[(size_t)N_NODES * 128];   // xw fp16 [N][128 half2]
__device__ float    g_res[(size_t)N_NODES * OUT_CH]; // residual fp32
__device__ float    g_alog[N_NODES * 8];
__device__ float    g_den[N_NODES * HEADS];
__device__ float4   g_ew[EN_TOT];
__device__ float    g_acc[(size_t)N_NODES * OUT_CH];
__device__ int      g_cnt[N_NODES];
__device__ int      g_bsum[SBLK];
__device__ int2     g_edges[EN_TOT];        // DST-sorted (s,d)
__device__ int      g_is64;

// ---------------- helpers ----------------------------------------------------
__device__ __forceinline__ int edge_at(const void* ei, int is64, long long idx) {
    return is64 ? (int)((const long long*)ei)[idx] : ((const int*)ei)[idx];
}
__device__ __forceinline__ float lrelu(float a) {
    return (a > 0.f) ? a : NEG_SLOPE * a;
}
__device__ __forceinline__ void cvt_hl(float x, float y, uint32_t& h, uint32_t& l) {
    __nv_bfloat162 hb = __floats2bfloat162_rn(x, y);
    float2 hf = __bfloat1622float2(hb);
    __nv_bfloat162 lb = __floats2bfloat162_rn(x - hf.x, y - hf.y);
    h = *(uint32_t*)&hb;
    l = *(uint32_t*)&lb;
}
#define MMA_BF16(d, a, b0, b1)                                                \
    asm volatile(                                                             \
        "mma.sync.aligned.m16n8k16.row.col.f32.bf16.bf16.f32 "                \
        "{%0,%1,%2,%3}, {%4,%5,%6,%7}, {%8,%9}, {%0,%1,%2,%3};"               \
        : "+f"(d[0]), "+f"(d[1]), "+f"(d[2]), "+f"(d[3])                      \
        : "r"(a.x), "r"(a.y), "r"(a.z), "r"(a.w), "r"(b0), "r"(b1))
#define REDV4(p, v)                                                           \
    asm volatile("red.global.add.v4.f32 [%0], {%1,%2,%3,%4};"                 \
                 :: "l"(p), "f"((v).x), "f"((v).y), "f"((v).z), "f"((v).w)    \
                 : "memory")
#define CP16(saddr, gptr)                                                     \
    asm volatile("cp.async.cg.shared.global [%0], [%1], 16;"                  \
                 :: "r"(saddr), "l"(gptr) : "memory")
#define CP_COMMIT() asm volatile("cp.async.commit_group;" ::: "memory")
#define CP_WAIT1()  asm volatile("cp.async.wait_group 1;" ::: "memory")
#define CP_WAIT0()  asm volatile("cp.async.wait_group 0;" ::: "memory")

// ---------------- k_detect ----------------------------------------------------
__global__ void k_detect(const unsigned* __restrict__ ei_words) {
    __shared__ unsigned s_or;
    if (threadIdx.x == 0) s_or = 0;
    __syncthreads();
    unsigned v = 0;
    for (int i = threadIdx.x; i < 4096; i += blockDim.x)
        v |= ei_words[2 * i + 1];
    if (v) atomicOr(&s_or, 1u);
    __syncthreads();
    if (threadIdx.x == 0) g_is64 = (s_or == 0) ? 1 : 0;
}

// ---------------- k_init -------------------------------------------------------
__global__ void k_init() {
    long long idx = blockIdx.x * (long long)blockDim.x + threadIdx.x;
    long long stride = (long long)gridDim.x * blockDim.x;
    long long nacc4 = (long long)N_NODES * OUT_CH / 4;
    float4 z = make_float4(0.f, 0.f, 0.f, 0.f);
    for (long long i = idx; i < nacc4; i += stride) ((float4*)g_acc)[i] = z;
    for (long long i = idx; i < (long long)N_NODES * HEADS; i += stride)
        g_den[i] = 0.f;
    for (long long i = idx; i < N_NODES; i += stride) g_cnt[i] = 0;
}

// ---------------- counting sort by DST -----------------------------------------
__global__ void k_hist(const void* __restrict__ ei) {
    int is64 = g_is64;
    int e = blockIdx.x * blockDim.x + threadIdx.x;
    if (e >= EN_TOT) return;
    int d = (e < E_EDGES) ? edge_at(ei, is64, E_EDGES + e) : e - E_EDGES;
    atomicAdd(&g_cnt[d], 1);
}

__global__ void k_scanA() {
    __shared__ int sh[256];
    int t = threadIdx.x;
    int idx = blockIdx.x * 256 + t;
    int v = (idx < N_NODES) ? g_cnt[idx] : 0;
    sh[t] = v;
    __syncthreads();
#pragma unroll
    for (int off = 1; off < 256; off <<= 1) {
        int u = (t >= off) ? sh[t - off] : 0;
        __syncthreads();
        sh[t] += u;
        __syncthreads();
    }
    if (idx < N_NODES) g_cnt[idx] = sh[t] - v;
    if (t == 255) g_bsum[blockIdx.x] = sh[255];
}

__global__ void k_scanB() {
    __shared__ int sh[256];
    int t = threadIdx.x;
    int v = (t < SBLK) ? g_bsum[t] : 0;
    sh[t] = v;
    __syncthreads();
#pragma unroll
    for (int off = 1; off < 256; off <<= 1) {
        int u = (t >= off) ? sh[t - off] : 0;
        __syncthreads();
        sh[t] += u;
        __syncthreads();
    }
    if (t < SBLK) g_bsum[t] = sh[t] - v;
}

__global__ void k_scanC() {
    int idx = blockIdx.x * blockDim.x + threadIdx.x;
    if (idx < N_NODES) g_cnt[idx] += g_bsum[idx >> 8];
}

__global__ void k_place(const void* __restrict__ ei) {
    int is64 = g_is64;
    int e = blockIdx.x * blockDim.x + threadIdx.x;
    if (e >= EN_TOT) return;
    int s, d;
    if (e < E_EDGES) {
        s = edge_at(ei, is64, e);
        d = edge_at(ei, is64, E_EDGES + e);
    } else {
        s = d = e - E_EDGES;
    }
    int pos = atomicAdd(&g_cnt[d], 1);
    g_edges[pos] = make_int2(s, d);
}

// ---------------- k_prep: X -> bf16 hi/lo fragments ----------------------------
__global__ void k_prep(const float* __restrict__ X) {
    int t = blockIdx.x * blockDim.x + threadIdx.x;
    if (t >= MBLK * 4096) return;
    int lane = t & 31;
    int mt = (t >> 5) & 7;
    int ks = (t >> 8) & 1;
    int kc = (t >> 9) & 7;
    int mb = t >> 12;

    int r0 = mb * 128 + mt * 16 + (lane >> 2);
    int tt = lane & 3;
    int k0 = kc * 32 + (ks * 8 + tt) * 2;

    float2 v[4];
    v[0] = (r0 < N_NODES) ? *(const float2*)(X + (size_t)r0 * IN_CH + k0)
                          : make_float2(0.f, 0.f);
    v[1] = (r0 + 8 < N_NODES) ? *(const float2*)(X + (size_t)(r0 + 8) * IN_CH + k0)
                              : make_float2(0.f, 0.f);
    v[2] = (r0 < N_NODES) ? *(const float2*)(X + (size_t)r0 * IN_CH + k0 + 8)
                          : make_float2(0.f, 0.f);
    v[3] = (r0 + 8 < N_NODES) ? *(const float2*)(X + (size_t)(r0 + 8) * IN_CH + k0 + 8)
                              : make_float2(0.f, 0.f);
    uint4 hv, lv;
    cvt_hl(v[0].x, v[0].y, hv.x, lv.x);
    cvt_hl(v[1].x, v[1].y, hv.y, lv.y);
    cvt_hl(v[2].x, v[2].y, hv.z, lv.z);
    cvt_hl(v[3].x, v[3].y, hv.w, lv.w);

    int base = mb * 8192 + kc * 1024 + ks * 256 + mt * 32 + lane;
    g_Af[base] = hv;
    g_Af[base + 512] = lv;
}

// ---------------- k_packB ------------------------------------------------------
__global__ void k_packB(const float* __restrict__ W, const float* __restrict__ Wr) {
    int t = blockIdx.x * blockDim.x + threadIdx.x;
    if (t >= 5 * 4096) return;
    int lane = t & 31;
    int nt = (t >> 5) & 7;
    int ks = (t >> 8) & 1;
    int kc = (t >> 9) & 7;
    int nb = t >> 12;

    int col = nb * 64 + nt * 8 + (lane >> 2);
    int tt = lane & 3;
    int k0 = kc * 32 + ks * 16 + tt * 2;

    float b00, b01, b10, b11;
    if (col < HC) {
        b00 = W[(k0) * HC + col];     b01 = W[(k0 + 1) * HC + col];
        b10 = W[(k0 + 8) * HC + col]; b11 = W[(k0 + 9) * HC + col];
    } else {
        int c = col - HC;
        b00 = Wr[(k0) * OUT_CH + c];     b01 = Wr[(k0 + 1) * OUT_CH + c];
        b10 = Wr[(k0 + 8) * OUT_CH + c]; b11 = Wr[(k0 + 9) * OUT_CH + c];
    }
    uint4 o;
    cvt_hl(b00, b01, o.x, o.z);
    cvt_hl(b10, b11, o.y, o.w);
    g_Bf[nb * 4096 + kc * 512 + ks * 256 + nt * 32 + lane] = o;
}

// ---------------- k_gemm: A-resident in smem, loop nb, B double-buffered ------
// grid = MBLK (1 CTA per 128 rows). dyn smem: A 8192 uint4 + B 2x512 = 147456 B
__global__ __launch_bounds__(256) void k_gemm(const float* __restrict__ att_src,
                                              const float* __restrict__ att_dst) {
    extern __shared__ uint4 smemu[];
    uint4* sAf = smemu;            // 8192 uint4 (128 KB)
    uint4* sB = smemu + 8192;      // 2 x 512 uint4
    __shared__ float sAttS[256], sAttD[256], sA[128], sD[128];

    int tid = threadIdx.x;
    int lane = tid & 31;
    int wid = tid >> 5;
    int mrow = wid >> 1;           // 0..3
    int ncol = wid & 1;            // 0..1
    int mb = blockIdx.x;

    sAttS[tid] = att_src[tid];
    sAttD[tid] = att_dst[tid];
    if (tid < 128) { sA[tid] = 0.f; sD[tid] = 0.f; }

    const uint4* Ab = g_Af + mb * 8192;
    uint32_t sA32 = (uint32_t)__cvta_generic_to_shared(sAf);
    uint32_t sB32 = (uint32_t)__cvta_generic_to_shared(sB);

    auto issueA = [&](int kc) {
        const uint4* gA = Ab + kc * 1024;
        uint32_t dst = sA32 + kc * 1024 * 16;
#pragma unroll
        for (int i = 0; i < 4; i++)
            CP16(dst + (tid + 256 * i) * 16, gA + tid + 256 * i);
    };
    auto issueB = [&](int nb, int kc) {
        const uint4* gB = g_Bf + nb * 4096 + kc * 512;
        uint32_t dst = sB32 + (kc & 1) * 512 * 16;
#pragma unroll
        for (int i = 0; i < 2; i++)
            CP16(dst + (tid + 256 * i) * 16, gB + tid + 256 * i);
    };

    float acc[2][4][4];

    auto compute = [&](int kc) {
        const uint4* bufA = sAf + kc * 1024;
        const uint4* bufB = sB + (kc & 1) * 512;
        uint4 ah[2][2], al[2][2];
#pragma unroll
        for (int ks = 0; ks < 2; ks++)
#pragma unroll
            for (int mt = 0; mt < 2; mt++) {
                int m = mrow * 2 + mt;
                ah[ks][mt] = bufA[ks * 256 + m * 32 + lane];
                al[ks][mt] = bufA[512 + ks * 256 + m * 32 + lane];
            }
#pragma unroll
        for (int ks = 0; ks < 2; ks++)
#pragma unroll
            for (int j = 0; j < 4; j++) {
                uint4 bv = bufB[ks * 256 + (ncol * 4 + j) * 32 + lane];
#pragma unroll
                for (int mt = 0; mt < 2; mt++) {
                    MMA_BF16(acc[mt][j], ah[ks][mt], bv.x, bv.y);
                    MMA_BF16(acc[mt][j], ah[ks][mt], bv.z, bv.w);
                    MMA_BF16(acc[mt][j], al[ks][mt], bv.x, bv.y);
                }
            }
    };

    auto epilogue = [&](int nb) {
#pragma unroll
        for (int mt = 0; mt < 2; mt++)
#pragma unroll
            for (int nt = 0; nt < 4; nt++) {
                int lr0 = (mrow * 2 + mt) * 16 + (lane >> 2);
                int row0 = mb * 128 + lr0;
                int colg = (ncol * 4 + nt) * 8 + (lane & 3) * 2;   // 0..63
                if (nb < 4) {
                    int hidx = (nb * 64 + colg) >> 1;
                    if (row0 < N_NODES)
                        g_outh[(size_t)row0 * 128 + hidx] =
                            __floats2half2_rn(acc[mt][nt][0], acc[mt][nt][1]);
                    if (row0 + 8 < N_NODES)
                        g_outh[(size_t)(row0 + 8) * 128 + hidx] =
                            __floats2half2_rn(acc[mt][nt][2], acc[mt][nt][3]);
                } else {
                    float* p = g_res + (size_t)row0 * OUT_CH + colg;
                    if (row0 < N_NODES)
                        *(float2*)p = make_float2(acc[mt][nt][0], acc[mt][nt][1]);
                    if (row0 + 8 < N_NODES)
                        *(float2*)(p + 8 * OUT_CH) =
                            make_float2(acc[mt][nt][2], acc[mt][nt][3]);
                }
            }
        if (nb < 4) {
#pragma unroll
            for (int mt = 0; mt < 2; mt++) {
                float s0 = 0.f, d0 = 0.f, s1 = 0.f, d1 = 0.f;
#pragma unroll
                for (int nt = 0; nt < 4; nt++) {
                    int cl = (ncol * 4 + nt) * 8 + (lane & 3) * 2;
                    float a0 = sAttS[nb * 64 + cl], a1 = sAttS[nb * 64 + cl + 1];
                    float b0 = sAttD[nb * 64 + cl], b1 = sAttD[nb * 64 + cl + 1];
                    s0 += acc[mt][nt][0] * a0 + acc[mt][nt][1] * a1;
                    s1 += acc[mt][nt][2] * a0 + acc[mt][nt][3] * a1;
                    d0 += acc[mt][nt][0] * b0 + acc[mt][nt][1] * b1;
                    d1 += acc[mt][nt][2] * b0 + acc[mt][nt][3] * b1;
                }
#pragma unroll
                for (int o = 1; o < 4; o <<= 1) {
                    s0 += __shfl_xor_sync(0xffffffffu, s0, o);
                    s1 += __shfl_xor_sync(0xffffffffu, s1, o);
                    d0 += __shfl_xor_sync(0xffffffffu, d0, o);
                    d1 += __shfl_xor_sync(0xffffffffu, d1, o);
                }
                if ((lane & 3) == 0) {
                    int r = (mrow * 2 + mt) * 16 + (lane >> 2);
                    atomicAdd(&sA[r], s0);
                    atomicAdd(&sD[r], d0);
                    atomicAdd(&sA[r + 8], s1);
                    atomicAdd(&sD[r + 8], d1);
                }
            }
            __syncthreads();
            for (int r = tid; r < 128; r += 256) {
                int n = mb * 128 + r;
                if (n < N_NODES) {
                    g_alog[n * 8 + nb] = sA[r];
                    g_alog[n * 8 + 4 + nb] = sD[r];
                }
                sA[r] = 0.f;
                sD[r] = 0.f;
            }
            __syncthreads();
        }
    };

    // ---- phase 1: nb=0, load A(kc) + B(0,kc) pipelined ----
    issueA(0); issueB(0, 0); CP_COMMIT();
#pragma unroll
    for (int i = 0; i < 2; i++)
#pragma unroll
        for (int j = 0; j < 4; j++)
#pragma unroll
            for (int q = 0; q < 4; q++) acc[i][j][q] = 0.f;
#pragma unroll 1
    for (int kc = 0; kc < 8; kc++) {
        if (kc < 7) { issueA(kc + 1); issueB(0, kc + 1); CP_COMMIT(); CP_WAIT1(); }
        else CP_WAIT0();
        __syncthreads();
        compute(kc);
        __syncthreads();
    }
    issueB(1, 0); CP_COMMIT();      // prefetch next nb under epilogue
    epilogue(0);

    // ---- phases 2-5: nb=1..4, B-only double buffer, A from smem ----
#pragma unroll 1
    for (int nb = 1; nb < 5; nb++) {
#pragma unroll
        for (int i = 0; i < 2; i++)
#pragma unroll
            for (int j = 0; j < 4; j++)
#pragma unroll
                for (int q = 0; q < 4; q++) acc[i][j][q] = 0.f;
#pragma unroll 1
        for (int kc = 0; kc < 8; kc++) {
            if (kc < 7) { issueB(nb, kc + 1); CP_COMMIT(); CP_WAIT1(); }
            else CP_WAIT0();
            __syncthreads();
            compute(kc);
            __syncthreads();
        }
        if (nb < 4) { issueB(nb + 1, 0); CP_COMMIT(); }
        epilogue(nb);
    }
}

// ---------------- k_sum: 1 thread = ECHUNK dst-sorted edges --------------------
__global__ void k_sum() {
    long long g = blockIdx.x * (long long)blockDim.x + threadIdx.x;
    long long e0 = g * ECHUNK;
    if (e0 >= EN_TOT) return;
    float4 acc = make_float4(0.f, 0.f, 0.f, 0.f);
    int dprev = -1;
#pragma unroll
    for (int i = 0; i < ECHUNK; i++) {
        long long e = e0 + i;
        if (e >= EN_TOT) break;
        int2 ed = g_edges[e];
        float4 as = *(const float4*)(g_alog + ed.x * 8);
        float4 ad = *(const float4*)(g_alog + ed.y * 8 + 4);
        float4 ex;
        ex.x = __expf(lrelu(as.x + ad.x));
        ex.y = __expf(lrelu(as.y + ad.y));
        ex.z = __expf(lrelu(as.z + ad.z));
        ex.w = __expf(lrelu(as.w + ad.w));
        g_ew[e] = ex;
        if (ed.y != dprev) {
            if (dprev >= 0) REDV4(g_den + dprev * 4, acc);
            acc = ex;
            dprev = ed.y;
        } else {
            acc.x += ex.x; acc.y += ex.y; acc.z += ex.z; acc.w += ex.w;
        }
    }
    if (dprev >= 0) REDV4(g_den + dprev * 4, acc);
}

// ---------------- k_invden -----------------------------------------------------
__global__ void k_invden() {
    int i = blockIdx.x * blockDim.x + threadIdx.x;
    if (i < N_NODES * HEADS) g_den[i] = 1.0f / g_den[i];
}

// ---------------- k_scatter: fp16 gather, 16 lanes x SCHUNK edges --------------
__global__ void k_scatter() {
    int lane = threadIdx.x & 31;
    int sub = lane & 15;
    long long grp = ((long long)blockIdx.x * blockDim.x + threadIdx.x) >> 4;
    long long e0 = grp * SCHUNK;
    if (e0 >= EN_TOT) return;
    int c0 = sub * 4;

    float4 acc = make_float4(0.f, 0.f, 0.f, 0.f);
    int dprev = -1;
#pragma unroll 8
    for (int i = 0; i < SCHUNK; i++) {
        long long e = e0 + i;
        if (e >= EN_TOT) break;
        int2 ed = g_edges[e];
        float4 w = g_ew[e];
        float4 dn = *(const float4*)(g_den + ed.y * 4);
        float wh[4] = {w.x * dn.x, w.y * dn.y, w.z * dn.z, w.w * dn.w};

        if (ed.y != dprev) {
            if (dprev >= 0)
                REDV4(g_acc + (size_t)dprev * OUT_CH + c0, acc);
            acc = make_float4(0.f, 0.f, 0.f, 0.f);
            dprev = ed.y;
        }
#pragma unroll
        for (int h = 0; h < 4; h++) {
            uint2 raw = *(const uint2*)(g_outh + (size_t)ed.x * 128 + h * 32 + sub * 2);
            float2 a = __half22float2(*(__half2*)&raw.x);
            float2 b = __half22float2(*(__half2*)&raw.y);
            acc.x = fmaf(wh[h], a.x, acc.x);
            acc.y = fmaf(wh[h], a.y, acc.y);
            acc.z = fmaf(wh[h], b.x, acc.z);
            acc.w = fmaf(wh[h], b.y, acc.w);
        }
    }
    if (dprev >= 0)
        REDV4(g_acc + (size_t)dprev * OUT_CH + c0, acc);
}

// ---------------- k_final ------------------------------------------------------
__global__ void k_final(const float* __restrict__ bias, float* __restrict__ out) {
    int i = blockIdx.x * blockDim.x + threadIdx.x;
    if (i >= N_NODES * 16) return;
    int n = i >> 4;
    int c = (i & 15) * 4;
    float4 a = *(const float4*)(g_acc + (size_t)n * OUT_CH + c);
    float4 b = *(const float4*)(bias + c);
    float4 r = *(const float4*)(g_res + (size_t)n * OUT_CH + c);
    float4 o;
    o.x = fmaxf(0.f, 0.25f * a.x + b.x + r.x);
    o.y = fmaxf(0.f, 0.25f * a.y + b.y + r.y);
    o.z = fmaxf(0.f, 0.25f * a.z + b.z + r.z);
    o.w = fmaxf(0.f, 0.25f * a.w + b.w + r.w);
    *(float4*)(out + (size_t)n * OUT_CH + c) = o;
}

// ---------------- launch -------------------------------------------------------
extern "C" void kernel_launch(void* const* d_in, const int* in_sizes, int n_in,
                              void* d_out, int out_size) {
    const float* x       = (const float*)d_in[0];
    const void*  ei      = d_in[1];
    const float* W       = (const float*)d_in[2];
    const float* att_src = (const float*)d_in[3];
    const float* att_dst = (const float*)d_in[4];
    const float* bias    = (const float*)d_in[5];
    const float* W_res   = (const float*)d_in[6];
    float* out = (float*)d_out;

    const int GSMEM = (8192 + 2 * 512) * 16;   // 147456 B
    static cudaStream_t s1;
    static cudaEvent_t evFork, evJoin;
    static int inited = 0;
    if (!inited) {
        cudaStreamCreateWithFlags(&s1, cudaStreamNonBlocking);
        cudaEventCreateWithFlags(&evFork, cudaEventDisableTiming);
        cudaEventCreateWithFlags(&evJoin, cudaEventDisableTiming);
        cudaFuncSetAttribute(k_gemm, cudaFuncAttributeMaxDynamicSharedMemorySize,
                             GSMEM);
        inited = 1;
    }

    k_detect<<<1, 256>>>((const unsigned*)ei);
    k_init<<<1024, 256>>>();

    // fork: sort chain on s1, GEMM chain on main stream
    cudaEventRecord(evFork, 0);
    cudaStreamWaitEvent(s1, evFork, 0);
    k_hist<<<(EN_TOT + 255) / 256, 256, 0, s1>>>(ei);
    k_scanA<<<SBLK, 256, 0, s1>>>();
    k_scanB<<<1, 256, 0, s1>>>();
    k_scanC<<<SBLK, 256, 0, s1>>>();
    k_place<<<(EN_TOT + 255) / 256, 256, 0, s1>>>(ei);
    cudaEventRecord(evJoin, s1);

    k_prep<<<(MBLK * 4096 + 255) / 256, 256>>>(x);
    k_packB<<<(5 * 4096 + 255) / 256, 256>>>(W, W_res);
    k_gemm<<<MBLK, 256, GSMEM>>>(att_src, att_dst);

    // join before edge phase
    cudaStreamWaitEvent(0, evJoin, 0);
    {
        long long ng = (EN_TOT + ECHUNK - 1) / ECHUNK;
        k_sum<<<(int)((ng + 255) / 256), 256>>>();
        k_invden<<<(N_NODES * HEADS + 255) / 256, 256>>>();
        long long ngs = (EN_TOT + SCHUNK - 1) / SCHUNK;
        k_scatter<<<(int)((ngs * 16 + 255) / 256), 256>>>();
    }
    k_final<<<(N_NODES * 16 + 255) / 256, 256>>>(bias, out);
}

// round 15
// speedup vs baseline: 1.1793x; 1.1793x over previous
#include <cuda_runtime.h>
#include <cuda_bf16.h>
#include <cuda_fp16.h>
#include <cstdint>

#define N_NODES 50000
#define E_EDGES 800000
#define EN_TOT  (E_EDGES + N_NODES)
#define IN_CH   256
#define OUT_CH  64
#define HEADS   4
#define HC      256
#define NEG_SLOPE 0.2f
#define MBLK    391            // ceil(50000/128)
#define SBLK    196            // ceil(50000/256)
#define ECHUNK  8              // edges per group in k_sum
#define SCHUNK  32             // edges per group in k_scatter

// ---------------- device scratch ---------------------------------------------
__device__ uint4    g_Af[MBLK * 8192];      // A frags [mb][kc8][hl2][ks2][mt8][lane32]
__device__ uint4    g_Bf[5 * 4096];         // B frags [nb5][kc8][ks2][nt8][lane32]
__device__ __half2  g_outh[(size_t)N_NODES * 128];   // xw fp16 [N][128 half2]
__device__ float    g_res[(size_t)N_NODES * OUT_CH]; // residual fp32
__device__ float    g_alog[N_NODES * 8];
__device__ float    g_den[N_NODES * HEADS];
__device__ float4   g_ew[EN_TOT];
__device__ float    g_acc[(size_t)N_NODES * OUT_CH];
__device__ int      g_cnt[N_NODES];
__device__ int      g_bsum[SBLK];
__device__ int2     g_edges[EN_TOT];        // DST-sorted (s,d)
__device__ int      g_is64;

// ---------------- helpers ----------------------------------------------------
__device__ __forceinline__ int edge_at(const void* ei, int is64, long long idx) {
    return is64 ? (int)((const long long*)ei)[idx] : ((const int*)ei)[idx];
}
__device__ __forceinline__ float lrelu(float a) {
    return (a > 0.f) ? a : NEG_SLOPE * a;
}
__device__ __forceinline__ void cvt_hl(float x, float y, uint32_t& h, uint32_t& l) {
    __nv_bfloat162 hb = __floats2bfloat162_rn(x, y);
    float2 hf = __bfloat1622float2(hb);
    __nv_bfloat162 lb = __floats2bfloat162_rn(x - hf.x, y - hf.y);
    h = *(uint32_t*)&hb;
    l = *(uint32_t*)&lb;
}
#define MMA_BF16(d, a, b0, b1)                                                \
    asm volatile(                                                             \
        "mma.sync.aligned.m16n8k16.row.col.f32.bf16.bf16.f32 "                \
        "{%0,%1,%2,%3}, {%4,%5,%6,%7}, {%8,%9}, {%0,%1,%2,%3};"               \
        : "+f"(d[0]), "+f"(d[1]), "+f"(d[2]), "+f"(d[3])                      \
        : "r"(a.x), "r"(a.y), "r"(a.z), "r"(a.w), "r"(b0), "r"(b1))
#define REDV4(p, v)                                                           \
    asm volatile("red.global.add.v4.f32 [%0], {%1,%2,%3,%4};"                 \
                 :: "l"(p), "f"((v).x), "f"((v).y), "f"((v).z), "f"((v).w)    \
                 : "memory")
#define CP16(saddr, gptr)                                                     \
    asm volatile("cp.async.cg.shared.global [%0], [%1], 16;"                  \
                 :: "r"(saddr), "l"(gptr) : "memory")
#define CP_COMMIT() asm volatile("cp.async.commit_group;" ::: "memory")
#define CP_WAIT1()  asm volatile("cp.async.wait_group 1;" ::: "memory")
#define CP_WAIT0()  asm volatile("cp.async.wait_group 0;" ::: "memory")

// ---------------- k_detect ----------------------------------------------------
__global__ void k_detect(const unsigned* __restrict__ ei_words) {
    __shared__ unsigned s_or;
    if (threadIdx.x == 0) s_or = 0;
    __syncthreads();
    unsigned v = 0;
    for (int i = threadIdx.x; i < 4096; i += blockDim.x)
        v |= ei_words[2 * i + 1];
    if (v) atomicOr(&s_or, 1u);
    __syncthreads();
    if (threadIdx.x == 0) g_is64 = (s_or == 0) ? 1 : 0;
}

// ---------------- k_init -------------------------------------------------------
__global__ void k_init() {
    long long idx = blockIdx.x * (long long)blockDim.x + threadIdx.x;
    long long stride = (long long)gridDim.x * blockDim.x;
    long long nacc4 = (long long)N_NODES * OUT_CH / 4;
    float4 z = make_float4(0.f, 0.f, 0.f, 0.f);
    for (long long i = idx; i < nacc4; i += stride) ((float4*)g_acc)[i] = z;
    for (long long i = idx; i < (long long)N_NODES * HEADS; i += stride)
        g_den[i] = 0.f;
    for (long long i = idx; i < N_NODES; i += stride) g_cnt[i] = 0;
}

// ---------------- counting sort by DST -----------------------------------------
__global__ void k_hist(const void* __restrict__ ei) {
    int is64 = g_is64;
    int e = blockIdx.x * blockDim.x + threadIdx.x;
    if (e >= EN_TOT) return;
    int d = (e < E_EDGES) ? edge_at(ei, is64, E_EDGES + e) : e - E_EDGES;
    atomicAdd(&g_cnt[d], 1);
}

__global__ void k_scanA() {
    __shared__ int sh[256];
    int t = threadIdx.x;
    int idx = blockIdx.x * 256 + t;
    int v = (idx < N_NODES) ? g_cnt[idx] : 0;
    sh[t] = v;
    __syncthreads();
#pragma unroll
    for (int off = 1; off < 256; off <<= 1) {
        int u = (t >= off) ? sh[t - off] : 0;
        __syncthreads();
        sh[t] += u;
        __syncthreads();
    }
    if (idx < N_NODES) g_cnt[idx] = sh[t] - v;
    if (t == 255) g_bsum[blockIdx.x] = sh[255];
}

__global__ void k_scanB() {
    __shared__ int sh[256];
    int t = threadIdx.x;
    int v = (t < SBLK) ? g_bsum[t] : 0;
    sh[t] = v;
    __syncthreads();
#pragma unroll
    for (int off = 1; off < 256; off <<= 1) {
        int u = (t >= off) ? sh[t - off] : 0;
        __syncthreads();
        sh[t] += u;
        __syncthreads();
    }
    if (t < SBLK) g_bsum[t] = sh[t] - v;
}

__global__ void k_scanC() {
    int idx = blockIdx.x * blockDim.x + threadIdx.x;
    if (idx < N_NODES) g_cnt[idx] += g_bsum[idx >> 8];
}

__global__ void k_place(const void* __restrict__ ei) {
    int is64 = g_is64;
    int e = blockIdx.x * blockDim.x + threadIdx.x;
    if (e >= EN_TOT) return;
    int s, d;
    if (e < E_EDGES) {
        s = edge_at(ei, is64, e);
        d = edge_at(ei, is64, E_EDGES + e);
    } else {
        s = d = e - E_EDGES;
    }
    int pos = atomicAdd(&g_cnt[d], 1);
    g_edges[pos] = make_int2(s, d);
}

// ---------------- k_prep: X -> bf16 hi/lo fragments ----------------------------
__global__ void k_prep(const float* __restrict__ X) {
    int t = blockIdx.x * blockDim.x + threadIdx.x;
    if (t >= MBLK * 4096) return;
    int lane = t & 31;
    int mt = (t >> 5) & 7;
    int ks = (t >> 8) & 1;
    int kc = (t >> 9) & 7;
    int mb = t >> 12;

    int r0 = mb * 128 + mt * 16 + (lane >> 2);
    int tt = lane & 3;
    int k0 = kc * 32 + (ks * 8 + tt) * 2;

    float2 v[4];
    v[0] = (r0 < N_NODES) ? *(const float2*)(X + (size_t)r0 * IN_CH + k0)
                          : make_float2(0.f, 0.f);
    v[1] = (r0 + 8 < N_NODES) ? *(const float2*)(X + (size_t)(r0 + 8) * IN_CH + k0)
                              : make_float2(0.f, 0.f);
    v[2] = (r0 < N_NODES) ? *(const float2*)(X + (size_t)r0 * IN_CH + k0 + 8)
                          : make_float2(0.f, 0.f);
    v[3] = (r0 + 8 < N_NODES) ? *(const float2*)(X + (size_t)(r0 + 8) * IN_CH + k0 + 8)
                              : make_float2(0.f, 0.f);
    uint4 hv, lv;
    cvt_hl(v[0].x, v[0].y, hv.x, lv.x);
    cvt_hl(v[1].x, v[1].y, hv.y, lv.y);
    cvt_hl(v[2].x, v[2].y, hv.z, lv.z);
    cvt_hl(v[3].x, v[3].y, hv.w, lv.w);

    int base = mb * 8192 + kc * 1024 + ks * 256 + mt * 32 + lane;
    g_Af[base] = hv;
    g_Af[base + 512] = lv;
}

// ---------------- k_packB ------------------------------------------------------
__global__ void k_packB(const float* __restrict__ W, const float* __restrict__ Wr) {
    int t = blockIdx.x * blockDim.x + threadIdx.x;
    if (t >= 5 * 4096) return;
    int lane = t & 31;
    int nt = (t >> 5) & 7;
    int ks = (t >> 8) & 1;
    int kc = (t >> 9) & 7;
    int nb = t >> 12;

    int col = nb * 64 + nt * 8 + (lane >> 2);
    int tt = lane & 3;
    int k0 = kc * 32 + ks * 16 + tt * 2;

    float b00, b01, b10, b11;
    if (col < HC) {
        b00 = W[(k0) * HC + col];     b01 = W[(k0 + 1) * HC + col];
        b10 = W[(k0 + 8) * HC + col]; b11 = W[(k0 + 9) * HC + col];
    } else {
        int c = col - HC;
        b00 = Wr[(k0) * OUT_CH + c];     b01 = Wr[(k0 + 1) * OUT_CH + c];
        b10 = Wr[(k0 + 8) * OUT_CH + c]; b11 = Wr[(k0 + 9) * OUT_CH + c];
    }
    uint4 o;
    cvt_hl(b00, b01, o.x, o.z);
    cvt_hl(b10, b11, o.y, o.w);
    g_Bf[nb * 4096 + kc * 512 + ks * 256 + nt * 32 + lane] = o;
}

// ---------------- k_gemm: cp.async 2-stage pipeline + fused logits ------------
__global__ __launch_bounds__(256) void k_gemm(const float* __restrict__ att_src,
                                              const float* __restrict__ att_dst) {
    extern __shared__ uint4 sbuf[];
    __shared__ float sAttS[64], sAttD[64], sA[128], sD[128];
    int tid = threadIdx.x;
    int lane = tid & 31;
    int wid = tid >> 5;
    int mrow = wid >> 1;
    int ncol = wid & 1;
    int mb = blockIdx.y;
    int nb = blockIdx.x;

    if (nb < 4) {
        if (tid < 64) {
            sAttS[tid] = att_src[nb * 64 + tid];
            sAttD[tid] = att_dst[nb * 64 + tid];
        }
        if (tid >= 64 && tid < 192) {
            sA[tid - 64] = 0.f;
            sD[tid - 64] = 0.f;
        }
    }

    const uint4* Ab = g_Af + mb * 8192;
    const uint4* Bb = g_Bf + nb * 4096;
    uint32_t sb32 = (uint32_t)__cvta_generic_to_shared(sbuf);

    auto issue = [&](int kc, int stage) {
        uint32_t sa = sb32 + (stage * 1536) * 16;
        const uint4* gA = Ab + kc * 1024;
#pragma unroll
        for (int i = 0; i < 4; i++)
            CP16(sa + (tid + 256 * i) * 16, gA + tid + 256 * i);
        uint32_t sbB = sb32 + (stage * 1536 + 1024) * 16;
        const uint4* gB = Bb + kc * 512;
#pragma unroll
        for (int i = 0; i < 2; i++)
            CP16(sbB + (tid + 256 * i) * 16, gB + tid + 256 * i);
        CP_COMMIT();
    };

    float acc[2][4][4];
#pragma unroll
    for (int i = 0; i < 2; i++)
#pragma unroll
        for (int j = 0; j < 4; j++)
#pragma unroll
            for (int q = 0; q < 4; q++) acc[i][j][q] = 0.f;

    issue(0, 0);

#pragma unroll 1
    for (int kc = 0; kc < 8; kc++) {
        if (kc < 7) {
            issue(kc + 1, (kc + 1) & 1);
            CP_WAIT1();
        } else {
            CP_WAIT0();
        }
        __syncthreads();
        const uint4* bufA = sbuf + (kc & 1) * 1536;
        const uint4* bufB = bufA + 1024;
        uint4 ah[2][2], al[2][2];
#pragma unroll
        for (int ks = 0; ks < 2; ks++)
#pragma unroll
            for (int mt = 0; mt < 2; mt++) {
                int m = mrow * 2 + mt;
                ah[ks][mt] = bufA[ks * 256 + m * 32 + lane];
                al[ks][mt] = bufA[512 + ks * 256 + m * 32 + lane];
            }
#pragma unroll
        for (int ks = 0; ks < 2; ks++)
#pragma unroll
            for (int j = 0; j < 4; j++) {
                uint4 bv = bufB[ks * 256 + (ncol * 4 + j) * 32 + lane];
#pragma unroll
                for (int mt = 0; mt < 2; mt++) {
                    MMA_BF16(acc[mt][j], ah[ks][mt], bv.x, bv.y);
                    MMA_BF16(acc[mt][j], ah[ks][mt], bv.z, bv.w);
                    MMA_BF16(acc[mt][j], al[ks][mt], bv.x, bv.y);
                }
            }
        __syncthreads();
    }

    // epilogue: xw -> fp16 g_outh (nb<4); residual -> fp32 g_res (nb==4)
#pragma unroll
    for (int mt = 0; mt < 2; mt++)
#pragma unroll
        for (int nt = 0; nt < 4; nt++) {
            int row0 = mb * 128 + (mrow * 2 + mt) * 16 + (lane >> 2);
            int colg = (ncol * 4 + nt) * 8 + (lane & 3) * 2;   // 0..63
            if (nb < 4) {
                int hidx = (nb * 64 + colg) >> 1;
                if (row0 < N_NODES)
                    g_outh[(size_t)row0 * 128 + hidx] =
                        __floats2half2_rn(acc[mt][nt][0], acc[mt][nt][1]);
                if (row0 + 8 < N_NODES)
                    g_outh[(size_t)(row0 + 8) * 128 + hidx] =
                        __floats2half2_rn(acc[mt][nt][2], acc[mt][nt][3]);
            } else {
                float* p = g_res + (size_t)row0 * OUT_CH + colg;
                if (row0 < N_NODES)
                    *(float2*)p = make_float2(acc[mt][nt][0], acc[mt][nt][1]);
                if (row0 + 8 < N_NODES)
                    *(float2*)(p + 8 * OUT_CH) =
                        make_float2(acc[mt][nt][2], acc[mt][nt][3]);
            }
        }

    if (nb < 4) {
#pragma unroll
        for (int mt = 0; mt < 2; mt++) {
            float s0 = 0.f, d0 = 0.f, s1 = 0.f, d1 = 0.f;
#pragma unroll
            for (int nt = 0; nt < 4; nt++) {
                int cl = (ncol * 4 + nt) * 8 + (lane & 3) * 2;
                float a0 = sAttS[cl], a1 = sAttS[cl + 1];
                float b0 = sAttD[cl], b1 = sAttD[cl + 1];
                s0 += acc[mt][nt][0] * a0 + acc[mt][nt][1] * a1;
                s1 += acc[mt][nt][2] * a0 + acc[mt][nt][3] * a1;
                d0 += acc[mt][nt][0] * b0 + acc[mt][nt][1] * b1;
                d1 += acc[mt][nt][2] * b0 + acc[mt][nt][3] * b1;
            }
#pragma unroll
            for (int o = 1; o < 4; o <<= 1) {
                s0 += __shfl_xor_sync(0xffffffffu, s0, o);
                s1 += __shfl_xor_sync(0xffffffffu, s1, o);
                d0 += __shfl_xor_sync(0xffffffffu, d0, o);
                d1 += __shfl_xor_sync(0xffffffffu, d1, o);
            }
            if ((lane & 3) == 0) {
                int r = (mrow * 2 + mt) * 16 + (lane >> 2);
                atomicAdd(&sA[r], s0);
                atomicAdd(&sD[r], d0);
                atomicAdd(&sA[r + 8], s1);
                atomicAdd(&sD[r + 8], d1);
            }
        }
        __syncthreads();
        for (int r = tid; r < 128; r += 256) {
            int n = mb * 128 + r;
            if (n < N_NODES) {
                g_alog[n * 8 + nb] = sA[r];
                g_alog[n * 8 + 4 + nb] = sD[r];
            }
        }
    }
}

// ---------------- k_sum: 1 thread = ECHUNK dst-sorted edges --------------------
__global__ void k_sum() {
    long long g = blockIdx.x * (long long)blockDim.x + threadIdx.x;
    long long e0 = g * ECHUNK;
    if (e0 >= EN_TOT) return;
    float4 acc = make_float4(0.f, 0.f, 0.f, 0.f);
    int dprev = -1;
#pragma unroll
    for (int i = 0; i < ECHUNK; i++) {
        long long e = e0 + i;
        if (e >= EN_TOT) break;
        int2 ed = g_edges[e];
        float4 as = *(const float4*)(g_alog + ed.x * 8);
        float4 ad = *(const float4*)(g_alog + ed.y * 8 + 4);
        float4 ex;
        ex.x = __expf(lrelu(as.x + ad.x));
        ex.y = __expf(lrelu(as.y + ad.y));
        ex.z = __expf(lrelu(as.z + ad.z));
        ex.w = __expf(lrelu(as.w + ad.w));
        g_ew[e] = ex;
        if (ed.y != dprev) {
            if (dprev >= 0) REDV4(g_den + dprev * 4, acc);
            acc = ex;
            dprev = ed.y;
        } else {
            acc.x += ex.x; acc.y += ex.y; acc.z += ex.z; acc.w += ex.w;
        }
    }
    if (dprev >= 0) REDV4(g_den + dprev * 4, acc);
}

// ---------------- k_invden -----------------------------------------------------
__global__ void k_invden() {
    int i = blockIdx.x * blockDim.x + threadIdx.x;
    if (i < N_NODES * HEADS) g_den[i] = 1.0f / g_den[i];
}

// ---------------- k_scatter: fp16 gather, 16 lanes x SCHUNK edges --------------
__global__ void k_scatter() {
    int lane = threadIdx.x & 31;
    int sub = lane & 15;
    long long grp = ((long long)blockIdx.x * blockDim.x + threadIdx.x) >> 4;
    long long e0 = grp * SCHUNK;
    if (e0 >= EN_TOT) return;
    int c0 = sub * 4;

    float4 acc = make_float4(0.f, 0.f, 0.f, 0.f);
    int dprev = -1;
#pragma unroll 8
    for (int i = 0; i < SCHUNK; i++) {
        long long e = e0 + i;
        if (e >= EN_TOT) break;
        int2 ed = g_edges[e];
        float4 w = g_ew[e];
        float4 dn = *(const float4*)(g_den + ed.y * 4);
        float wh[4] = {w.x * dn.x, w.y * dn.y, w.z * dn.z, w.w * dn.w};

        if (ed.y != dprev) {
            if (dprev >= 0)
                REDV4(g_acc + (size_t)dprev * OUT_CH + c0, acc);
            acc = make_float4(0.f, 0.f, 0.f, 0.f);
            dprev = ed.y;
        }
#pragma unroll
        for (int h = 0; h < 4; h++) {
            uint2 raw = *(const uint2*)(g_outh + (size_t)ed.x * 128 + h * 32 + sub * 2);
            float2 a = __half22float2(*(__half2*)&raw.x);
            float2 b = __half22float2(*(__half2*)&raw.y);
            acc.x = fmaf(wh[h], a.x, acc.x);
            acc.y = fmaf(wh[h], a.y, acc.y);
            acc.z = fmaf(wh[h], b.x, acc.z);
            acc.w = fmaf(wh[h], b.y, acc.w);
        }
    }
    if (dprev >= 0)
        REDV4(g_acc + (size_t)dprev * OUT_CH + c0, acc);
}

// ---------------- k_final ------------------------------------------------------
__global__ void k_final(const float* __restrict__ bias, float* __restrict__ out) {
    int i = blockIdx.x * blockDim.x + threadIdx.x;
    if (i >= N_NODES * 16) return;
    int n = i >> 4;
    int c = (i & 15) * 4;
    float4 a = *(const float4*)(g_acc + (size_t)n * OUT_CH + c);
    float4 b = *(const float4*)(bias + c);
    float4 r = *(const float4*)(g_res + (size_t)n * OUT_CH + c);
    float4 o;
    o.x = fmaxf(0.f, 0.25f * a.x + b.x + r.x);
    o.y = fmaxf(0.f, 0.25f * a.y + b.y + r.y);
    o.z = fmaxf(0.f, 0.25f * a.z + b.z + r.z);
    o.w = fmaxf(0.f, 0.25f * a.w + b.w + r.w);
    *(float4*)(out + (size_t)n * OUT_CH + c) = o;
}

// ---------------- launch -------------------------------------------------------
extern "C" void kernel_launch(void* const* d_in, const int* in_sizes, int n_in,
                              void* d_out, int out_size) {
    const float* x       = (const float*)d_in[0];
    const void*  ei      = d_in[1];
    const float* W       = (const float*)d_in[2];
    const float* att_src = (const float*)d_in[3];
    const float* att_dst = (const float*)d_in[4];
    const float* bias    = (const float*)d_in[5];
    const float* W_res   = (const float*)d_in[6];
    float* out = (float*)d_out;

    static cudaStream_t s1;
    static cudaEvent_t evFork, evJoin;
    static int inited = 0;
    if (!inited) {
        cudaStreamCreateWithFlags(&s1, cudaStreamNonBlocking);
        cudaEventCreateWithFlags(&evFork, cudaEventDisableTiming);
        cudaEventCreateWithFlags(&evJoin, cudaEventDisableTiming);
        cudaFuncSetAttribute(k_gemm, cudaFuncAttributeMaxDynamicSharedMemorySize,
                             2 * 1536 * 16);
        inited = 1;
    }
    const int GSMEM = 2 * 1536 * 16;   // 49152 B

    k_detect<<<1, 256>>>((const unsigned*)ei);
    k_init<<<1024, 256>>>();

    // fork: sort chain on s1, GEMM chain on main stream
    cudaEventRecord(evFork, 0);
    cudaStreamWaitEvent(s1, evFork, 0);
    k_hist<<<(EN_TOT + 255) / 256, 256, 0, s1>>>(ei);
    k_scanA<<<SBLK, 256, 0, s1>>>();
    k_scanB<<<1, 256, 0, s1>>>();
    k_scanC<<<SBLK, 256, 0, s1>>>();
    k_place<<<(EN_TOT + 255) / 256, 256, 0, s1>>>(ei);
    cudaEventRecord(evJoin, s1);

    k_prep<<<(MBLK * 4096 + 255) / 256, 256>>>(x);
    k_packB<<<(5 * 4096 + 255) / 256, 256>>>(W, W_res);
    dim3 ggrid(5, MBLK);
    k_gemm<<<ggrid, 256, GSMEM>>>(att_src, att_dst);

    // join before edge phase
    cudaStreamWaitEvent(0, evJoin, 0);
    {
        long long ng = (EN_TOT + ECHUNK - 1) / ECHUNK;
        k_sum<<<(int)((ng + 255) / 256), 256>>>();
        k_invden<<<(N_NODES * HEADS + 255) / 256, 256>>>();
        long long ngs = (EN_TOT + SCHUNK - 1) / SCHUNK;
        k_scatter<<<(int)((ngs * 16 + 255) / 256), 256>>>();
    }
    k_final<<<(N_NODES * 16 + 255) / 256, 256>>>(bias, out);
}